// round 11
// baseline (speedup 1.0000x reference)
#include <cuda_runtime.h>
#include <cstdint>

// ForwardKinematics: B=262144 hand FK chains.
// CONFIRMED bit-exact reference model (Output0 rel_err == 0.0 in R10):
//  - sin/cos: glibc (ARM optimized-routines) scalar sinf/cosf — double
//    internal, nearest-even pi/2 reduction, fmadd-contracted polys.
//  - rot compose + chain einsum dots: fma-contracted ascending-k,
//    fma(a2,b2, fma(a1,b1, a0*b0)).
//  - elementwise HLO ops (p + bone*Rcol, pos*irbl + root): separate mul/add.
// THIS ROUND'S single change: projection einsum ('bij,bnj->bin') dot is
// elementally emitted -> separate mul/add, left-associated:
//    ((k0*a0 + k1*a1) + k2*a2)
// uv = q/qz is catastrophically ill-conditioned where qz ~ 0; only bit-exact
// qz reproduces the reference uv at the spikes.

#define FMUL(a, b) __fmul_rn((a), (b))
#define FADD(a, b) __fadd_rn((a), (b))
#define FMA3(a, b, c) __fmaf_rn((a), (b), (c))

// ---------------- glibc (ARM optimized-routines) sinf/cosf ----------------
#define GS_HPI_INV 0x1.45F306DC9C883p-1   // 2/pi
#define GS_HPI     0x1.921FB54442D18p0    // pi/2
#define GS_C0  0x1p0
#define GS_C1 -0x1.ffffffd0c621cp-2
#define GS_C2  0x1.55553e1068f19p-5
#define GS_C3 -0x1.6c087e89a359dp-10
#define GS_C4  0x1.99343027bf8c3p-16
#define GS_S1 -0x1.555545995a603p-3
#define GS_S2  0x1.1107605230bc4p-7
#define GS_S3 -0x1.994eb3774cf24p-13

__device__ __forceinline__ uint32_t abstop12(float y) {
    return (__float_as_uint(y) >> 20) & 0x7ffu;
}

__device__ __forceinline__ float gs_sinf_poly(double x, double x2, bool tbl1, int n) {
    if ((n & 1) == 0) {
        double x3 = x * x2;
        double s1 = __fma_rn(x2, GS_S3, GS_S2);
        double x7 = x3 * x2;
        double s  = __fma_rn(x3, GS_S1, x);
        return (float)__fma_rn(x7, s1, s);
    } else {
        double c0 = tbl1 ? -GS_C0 : GS_C0;
        double c1 = tbl1 ? -GS_C1 : GS_C1;
        double c2 = tbl1 ? -GS_C2 : GS_C2;
        double c3 = tbl1 ? -GS_C3 : GS_C3;
        double c4 = tbl1 ? -GS_C4 : GS_C4;
        double x4 = x2 * x2;
        double cc2 = __fma_rn(x2, c4, c3);
        double cc1 = __fma_rn(x2, c1, c0);
        double x6 = x4 * x2;
        double c   = __fma_rn(x4, c2, cc1);
        return (float)__fma_rn(x6, cc2, c);
    }
}

__device__ __forceinline__ double gs_sign(int m) {  // {1,-1,-1,1}[m&3]
    return (((m + 1) >> 1) & 1) ? -1.0 : 1.0;
}

__device__ __forceinline__ float glibc_sinf(float y) {
    const uint32_t t = abstop12(y);
    double x = (double)y;
    if (t < 0x3f4u) {
        if (t < 0x398u) return y;
        return gs_sinf_poly(x, x * x, false, 0);
    }
    double r  = x * GS_HPI_INV;
    double rn = rint(r);
    int    n  = (int)rn;
    double xr = __fma_rn(-rn, GS_HPI, x);
    double s = gs_sign(n);
    return gs_sinf_poly(xr * s, xr * xr, (n & 2) != 0, n);
}

__device__ __forceinline__ float glibc_cosf(float y) {
    const uint32_t t = abstop12(y);
    double x = (double)y;
    if (t < 0x3f4u) {
        if (t < 0x398u) return 1.0f;
        return gs_sinf_poly(x, x * x, false, 1);
    }
    double r  = x * GS_HPI_INV;
    double rn = rint(r);
    int    n  = (int)rn;
    double xr = __fma_rn(-rn, GS_HPI, x);
    int n1 = n + 1;
    double s = gs_sign(n1);
    return gs_sinf_poly(xr * s, xr * xr, (n1 & 2) != 0, n ^ 1);
}

// ---------------- FK chain: fma dots, mul/add elementwise ----------------

// fma-contracted ascending-k dot (chain/rot einsums — CONFIRMED)
__device__ __forceinline__ float dot3f(float a0, float b0, float a1, float b1,
                                       float a2, float b2) {
    return FMA3(a2, b2, FMA3(a1, b1, FMUL(a0, b0)));
}

// elemental mul/add dot (projection einsum — this round's change)
__device__ __forceinline__ float dot3m(float a0, float b0, float a1, float b1,
                                       float a2, float b2) {
    return FADD(FADD(FMUL(a0, b0), FMUL(a1, b1)), FMUL(a2, b2));
}

__device__ __forceinline__ void mm3f(const float A[3][3], const float Bm[3][3],
                                     float C[3][3]) {
#pragma unroll
    for (int i = 0; i < 3; i++)
#pragma unroll
        for (int j = 0; j < 3; j++)
            C[i][j] = dot3f(A[i][0], Bm[0][j], A[i][1], Bm[1][j], A[i][2], Bm[2][j]);
}

// L = (Rx @ Ry) @ Rz under fma-dot semantics, structural 0/1 folded
// (bit-neutral mod sign-of-zero).
__device__ __forceinline__ void rot_xyz(float sx, float cx, float sy, float cy,
                                        float sz, float cz, float L[3][3]) {
    float m10 = FMUL(sx, sy);     // (-sx)*(-sy)
    float m12 = FMUL(-sx, cy);
    float m20 = FMUL(cx, -sy);
    float m22 = FMUL(cx, cy);
    L[0][0] = FMUL(cy, cz);
    L[0][1] = FMUL(cy, -sz);
    L[0][2] = sy;
    L[1][0] = FMA3(cx, sz, FMUL(m10, cz));
    L[1][1] = FMA3(cx, cz, FMUL(m10, -sz));
    L[1][2] = m12;
    L[2][0] = FMA3(sx, sz, FMUL(m20, cz));
    L[2][1] = FMA3(sx, cz, FMUL(m20, -sz));
    L[2][2] = m22;
}

// R <- R @ L (general, fma dots)
__device__ __forceinline__ void rmul_full(float R[3][3], const float L[3][3]) {
    float T[3][3];
    mm3f(R, L, T);
#pragma unroll
    for (int i = 0; i < 3; i++)
#pragma unroll
        for (int j = 0; j < 3; j++) R[i][j] = T[i][j];
}

// R <- R @ Rx(s,c)  — bit-equal to full fma mm3 against literal Rx
__device__ __forceinline__ void rmul_rx(float R[3][3], float s, float c) {
#pragma unroll
    for (int i = 0; i < 3; i++) {
        float a1 = R[i][1], a2 = R[i][2];
        R[i][1] = FMA3(a2, s, FMUL(a1, c));
        R[i][2] = FMA3(a2, c, FMUL(a1, -s));
    }
}

// R <- R @ Ry(s,c)
__device__ __forceinline__ void rmul_ry(float R[3][3], float s, float c) {
#pragma unroll
    for (int i = 0; i < 3; i++) {
        float a0 = R[i][0], a2 = R[i][2];
        R[i][0] = FMA3(a2, -s, FMUL(a0, c));
        R[i][2] = FMA3(a2, c, FMUL(a0, s));
    }
}

// p <- p + bone * R[:,2]  (separate mul/add: elementwise HLO ops — CONFIRMED)
__device__ __forceinline__ void p_update(float p[3], const float R[3][3], float bone) {
#pragma unroll
    for (int i = 0; i < 3; i++) p[i] = FADD(p[i], FMUL(bone, R[i][2]));
}

__device__ __forceinline__ void emit_point(
    const float p[3], float irbl, const float root[3], const float K[3][3],
    float* __restrict__ out_abs, float* __restrict__ out_uv, int n) {
    float a[3];
#pragma unroll
    for (int i = 0; i < 3; i++) a[i] = FADD(FMUL(p[i], irbl), root[i]);
    out_abs[n * 3 + 0] = a[0];
    out_abs[n * 3 + 1] = a[1];
    out_abs[n * 3 + 2] = a[2];
    // projection einsum: elemental mul/add dot (this round's change)
    float q0 = dot3m(K[0][0], a[0], K[0][1], a[1], K[0][2], a[2]);
    float q1 = dot3m(K[1][0], a[0], K[1][1], a[1], K[1][2], a[2]);
    float q2 = dot3m(K[2][0], a[0], K[2][1], a[1], K[2][2], a[2]);
    float zr = (q2 == 0.0f) ? 1e-10f : q2;
    out_uv[n * 2 + 0] = __fdiv_rn(q0, zr);
    out_uv[n * 2 + 1] = __fdiv_rn(q1, zr);
}

__global__ __launch_bounds__(256)
void fk_kernel(const float* __restrict__ root_angles,
               const float* __restrict__ other_angles,
               const float* __restrict__ bone_lengths,
               const float* __restrict__ cam,
               const float* __restrict__ irbl_in,
               const float* __restrict__ root_xyz,
               float* __restrict__ out_abs_base,
               float* __restrict__ out_uv_base,
               int B)
{
    int b = blockIdx.x * blockDim.x + threadIdx.x;
    if (b >= B) return;

    float oa[23];
#pragma unroll
    for (int i = 0; i < 23; i++) oa[i] = other_angles[b * 23 + i];

    float bl[20];
#pragma unroll
    for (int i = 0; i < 20; i++) bl[i] = bone_lengths[b * 20 + i];

    float K[3][3];
#pragma unroll
    for (int i = 0; i < 3; i++)
#pragma unroll
        for (int j = 0; j < 3; j++) K[i][j] = cam[b * 9 + i * 3 + j];

    float irbl = irbl_in[b];
    float root[3];
#pragma unroll
    for (int i = 0; i < 3; i++) root[i] = root_xyz[b * 3 + i];

    float* out_abs = out_abs_base + (size_t)b * 63;
    float* out_uv  = out_uv_base  + (size_t)b * 42;

    // ---- root rotation ----
    float Rr[3][3];
    {
        float a0 = root_angles[b * 3 + 0];
        float a1 = root_angles[b * 3 + 1];
        float a2 = root_angles[b * 3 + 2];
        rot_xyz(glibc_sinf(a0), glibc_cosf(a0), glibc_sinf(a1), glibc_cosf(a1),
                glibc_sinf(a2), glibc_cosf(a2), Rr);
    }

    // keypoint 0 (wrist)
    {
        float p0[3] = {0.f, 0.f, 0.f};
        emit_point(p0, irbl, root, K, out_abs, out_uv, 0);
    }

    // Output keypoint index for finger f, level d: n = 1 + f*4 + (3 - d)
#pragma unroll
    for (int f = 0; f < 5; f++) {
        float R[3][3];
#pragma unroll
        for (int i = 0; i < 3; i++)
#pragma unroll
            for (int j = 0; j < 3; j++) R[i][j] = Rr[i][j];
        float p[3] = {0.f, 0.f, 0.f};
        float L[3][3];

        if (f == 0) {
            // thumb: d0=(oa0,oa1,oa2), d1=(oa3,oa4,oa5), d2=(0,oa6,0), d3=I
            rot_xyz(glibc_sinf(oa[0]), glibc_cosf(oa[0]),
                    glibc_sinf(oa[1]), glibc_cosf(oa[1]),
                    glibc_sinf(oa[2]), glibc_cosf(oa[2]), L);
            rmul_full(R, L);
            p_update(p, R, bl[0]);
            emit_point(p, irbl, root, K, out_abs, out_uv, 1 + 0 * 4 + 3);

            rot_xyz(glibc_sinf(oa[3]), glibc_cosf(oa[3]),
                    glibc_sinf(oa[4]), glibc_cosf(oa[4]),
                    glibc_sinf(oa[5]), glibc_cosf(oa[5]), L);
            rmul_full(R, L);
            p_update(p, R, bl[1]);
            emit_point(p, irbl, root, K, out_abs, out_uv, 1 + 0 * 4 + 2);

            // (0, oa6, 0): trig of 0 exact -> R@Ry
            rmul_ry(R, glibc_sinf(oa[6]), glibc_cosf(oa[6]));
            p_update(p, R, bl[2]);
            emit_point(p, irbl, root, K, out_abs, out_uv, 1 + 0 * 4 + 1);

            // identity level: R unchanged (R@I exact under fma dots)
            p_update(p, R, bl[3]);
            emit_point(p, irbl, root, K, out_abs, out_uv, 1 + 0 * 4 + 0);
        } else {
            const float o0 = oa[7 + (f - 1) * 4 + 0];
            const float o1 = oa[7 + (f - 1) * 4 + 1];
            const float o2 = oa[7 + (f - 1) * 4 + 2];
            const float o3 = oa[7 + (f - 1) * 4 + 3];

            // d0=(o0,o1,0): full rot with sz=0,cz=1 (fold bit-neutral)
            rot_xyz(glibc_sinf(o0), glibc_cosf(o0),
                    glibc_sinf(o1), glibc_cosf(o1), 0.f, 1.f, L);
            rmul_full(R, L);
            p_update(p, R, bl[f * 4 + 0]);
            emit_point(p, irbl, root, K, out_abs, out_uv, 1 + f * 4 + 3);

            // d1=(o2,0,0) -> R@Rx
            rmul_rx(R, glibc_sinf(o2), glibc_cosf(o2));
            p_update(p, R, bl[f * 4 + 1]);
            emit_point(p, irbl, root, K, out_abs, out_uv, 1 + f * 4 + 2);

            // d2=(o3,0,0) -> R@Rx
            rmul_rx(R, glibc_sinf(o3), glibc_cosf(o3));
            p_update(p, R, bl[f * 4 + 2]);
            emit_point(p, irbl, root, K, out_abs, out_uv, 1 + f * 4 + 1);

            // d3 identity
            p_update(p, R, bl[f * 4 + 3]);
            emit_point(p, irbl, root, K, out_abs, out_uv, 1 + f * 4 + 0);
        }
    }
}

extern "C" void kernel_launch(void* const* d_in, const int* in_sizes, int n_in,
                              void* d_out, int out_size)
{
    const float* root_angles  = (const float*)d_in[0];
    const float* other_angles = (const float*)d_in[1];
    const float* bone_lengths = (const float*)d_in[2];
    const float* cam          = (const float*)d_in[3];
    const float* irbl         = (const float*)d_in[4];
    const float* root_xyz     = (const float*)d_in[5];

    int B = in_sizes[0] / 3;

    float* out_abs = (float*)d_out;                   // (B,21,3)
    float* out_uv  = (float*)d_out + (size_t)B * 63;  // (B,21,2)

    int threads = 256;
    int blocks = (B + threads - 1) / threads;
    fk_kernel<<<blocks, threads>>>(root_angles, other_angles, bone_lengths,
                                   cam, irbl, root_xyz, out_abs, out_uv, B);
}